// round 6
// baseline (speedup 1.0000x reference)
#include <cuda_runtime.h>

// GCBFSafetyLayer: reference QP projection uses A = L_g_h = zeros, so every
// per-constraint update is gated off by (nrm > 1e-6) == false;
// safe_action == raw_action exactly (bit-identical, rel_err=0.0 measured).
// The task reduces to one 32 KB D2D move of d_in[3] -> d_out.
//
// Evidence of floor: kernel node (R4) and driver memcpy node (R5) both
// measured EXACTLY 4.575999us total — the duration is graph-replay +
// single-node dispatch overhead, not the copy. All grid>=8 kernel geometries
// are noise-equivalent (3.55-3.90us kernel); grid=1 regresses (single-SM
// L1tex queue). Final sweep point: 32 blocks x 64 threads, minimum per-SM
// sector queue depth, one wave. Expected neutral -> terminal optimum.

__global__ void __launch_bounds__(64, 1)
copy_exact_kernel(const float4* __restrict__ src, float4* __restrict__ dst) {
    int i = blockIdx.x * blockDim.x + threadIdx.x;
    dst[i] = src[i];
}

// Generic fallback for unexpected sizes.
__global__ void copy_generic_kernel(const float* __restrict__ src,
                                    float* __restrict__ dst, int n) {
    int i = blockIdx.x * blockDim.x + threadIdx.x;
    if (i < n) dst[i] = src[i];
}

extern "C" void kernel_launch(void* const* d_in, const int* in_sizes, int n_in,
                              void* d_out, int out_size) {
    const float* raw_action = (const float*)d_in[3];
    float* out = (float*)d_out;

    if ((out_size & 255) == 0) {
        // Multiple of 256 floats: grid = out_size/256 blocks of 64 threads,
        // one float4 per thread. For 8192 floats -> grid=32.
        int blocks = out_size / 256;
        copy_exact_kernel<<<blocks, 64>>>((const float4*)raw_action,
                                          (float4*)out);
    } else {
        int threads = 256;
        int blocks = (out_size + threads - 1) / threads;
        copy_generic_kernel<<<blocks, threads>>>(raw_action, out, out_size);
    }
}

// round 7
// speedup vs baseline: 1.4931x; 1.4931x over previous
#include <cuda_runtime.h>

// GCBFSafetyLayer — FINAL.
//
// The reference QP projection passes A = L_g_h = jnp.zeros(...) into the
// solver; every per-constraint update is gated by (nrm > 1e-6) where
// nrm = sum(a_j^2) = 0, so the gate is always false and lax.scan/fori_loop
// return u0 unchanged. safe_action == raw_action exactly (bit-identical;
// rel_err = 0.0 measured on every round). The task reduces to one 32 KB
// D2D move of d_in[3] -> d_out.
//
// Geometry sweep (kernel / total us):
//   1x256: 4.35/6.62   32x64: 4.22/6.88   8x256: 3.55/4.61
//   16x128: 3.78/4.58  memcpy node: -/4.58
// Kernel node (16x128) and driver memcpy node tie at exactly 4.575999us —
// that is the graph-replay + single-node dispatch floor; the copy itself
// (~8ns of HBM time) is invisible. This is the measured optimum.

__global__ void __launch_bounds__(128, 1)
copy_exact_kernel(const float4* __restrict__ src, float4* __restrict__ dst) {
    int i = blockIdx.x * blockDim.x + threadIdx.x;
    dst[i] = src[i];
}

// Generic fallback for unexpected sizes.
__global__ void copy_generic_kernel(const float* __restrict__ src,
                                    float* __restrict__ dst, int n) {
    int i = blockIdx.x * blockDim.x + threadIdx.x;
    if (i < n) dst[i] = src[i];
}

extern "C" void kernel_launch(void* const* d_in, const int* in_sizes, int n_in,
                              void* d_out, int out_size) {
    const float* raw_action = (const float*)d_in[3];
    float* out = (float*)d_out;

    if ((out_size & 511) == 0) {
        // Multiple of 512 floats: grid = out_size/512 blocks of 128 threads,
        // one float4 per thread. For 8192 floats -> grid=16 (measured best).
        int blocks = out_size / 512;
        copy_exact_kernel<<<blocks, 128>>>((const float4*)raw_action,
                                           (float4*)out);
    } else {
        int threads = 256;
        int blocks = (out_size + threads - 1) / threads;
        copy_generic_kernel<<<blocks, threads>>>(raw_action, out, out_size);
    }
}